// round 9
// baseline (speedup 1.0000x reference)
#include <cuda_runtime.h>
#include <cuda_bf16.h>
#include <cuda_fp16.h>
#include <math_constants.h>

#define NN 50000
#define NE 800000
#define HID 64
#define FULL 0xffffffffu

// ---------------------------------------------------------------------------
// Scratch (device globals; allocation-free per harness rules)
// ---------------------------------------------------------------------------
// Interleaved relation tables: row = 128 floats = [m_rel0 (64) | m_rel1 (64)]
__device__ __align__(16) float    g_mm  [NN * 128];   // conv1: n @ W1_rel[r]
__device__ __align__(16) float    g_pp  [NN * 128];   // conv2: h @ W2_rel[r]
__device__ __align__(16) float    g_r1  [NN * HID];   // n @ W1_root + b1
__device__ __align__(16) float    g_hpre[NN * HID];   // pre-relu h (conv1 out)
__device__ __align__(16) float    g_r2  [NN * HID];   // h @ W2_root + b2
// CSR by dst: record = {offset in float4 units (src*32+typ*16), half2(ea)}
__device__ int   g_deg[NN];
__device__ int   g_off[NN + 1];
__device__ int   g_cur[NN];
__device__ __align__(8) uint2 g_csr_ed[NE];

// ---------------------------------------------------------------------------
// Vectorized single-block scan (1024 thr, 4 elems/thread/pass)
// ---------------------------------------------------------------------------
__global__ void k_scan() {
    __shared__ int warpsum[32];
    int tid  = threadIdx.x;
    int lane = tid & 31;
    int wid  = tid >> 5;
    int carry = 0;
    for (int base = 0; base < NN; base += 4096) {
        int i0 = base + tid * 4;
        int v[4];
        #pragma unroll
        for (int j = 0; j < 4; j++) v[j] = (i0 + j < NN) ? g_deg[i0 + j] : 0;
        int tsum = (v[0] + v[1]) + (v[2] + v[3]);
        int s = tsum;
        #pragma unroll
        for (int o = 1; o < 32; o <<= 1) {
            int t = __shfl_up_sync(FULL, s, o);
            if (lane >= o) s += t;
        }
        if (lane == 31) warpsum[wid] = s;
        __syncthreads();
        if (wid == 0) {
            int ws = warpsum[lane];
            #pragma unroll
            for (int o = 1; o < 32; o <<= 1) {
                int t = __shfl_up_sync(FULL, ws, o);
                if (lane >= o) ws += t;
            }
            warpsum[lane] = ws;
        }
        __syncthreads();
        int wpre = (wid > 0) ? warpsum[wid - 1] : 0;
        int run  = carry + wpre + s - tsum;
        #pragma unroll
        for (int j = 0; j < 4; j++) {
            if (i0 + j < NN) { g_off[i0 + j] = run; g_cur[i0 + j] = run; run += v[j]; }
        }
        int total = warpsum[31];
        __syncthreads();
        carry += total;
    }
    if (tid == 0) g_off[NN] = NE;
}

// ---------------------------------------------------------------------------
// CSR fill (after scan): 8-byte records, offsets in float4 units
// ---------------------------------------------------------------------------
__global__ void k_fill(const int* __restrict__ ei,
                       const float* __restrict__ ea,
                       const int* __restrict__ et) {
    int e = blockIdx.x * blockDim.x + threadIdx.x;
    if (e >= NE) return;
    int dst = ei[NE + e];
    int pos = atomicAdd(&g_cur[dst], 1);
    unsigned off = (unsigned)ei[e] * 32u + (unsigned)et[e] * 16u;  // float4 units
    float2 a = ((const float2*)ea)[e];
    __half2 h = __floats2half2_rn(a.x, a.y);
    g_csr_ed[pos] = make_uint2(off, *reinterpret_cast<unsigned*>(&h));
}

// ---------------------------------------------------------------------------
// GEMM body (round-2 datapath):
//   o0/o1 -> interleaved table (row stride 128), o2 -> dense (stride 64, +bias)
// mode 0: f(in) = relu(x@Wn+bn) fused;  mode 1: f(in) = relu(in)
// ---------------------------------------------------------------------------
#define NPB 64
#define INPAD 68
#define GEMM_GRID ((NN + NPB - 1) / NPB)     // 782
extern __shared__ float s_dyn[];

__device__ __forceinline__ void gemm_body(
        int gblk,
        const float* __restrict__ in,
        const float* __restrict__ W0,
        const float* __restrict__ W1,
        const float* __restrict__ W2,
        const float* __restrict__ bias2,
        const float* __restrict__ Wn,
        const float* __restrict__ bn,
        float* __restrict__ oAB,     // interleaved table base (stride 128)
        float* __restrict__ o2,      // dense (stride 64)
        int mode) {
    float* sW  = s_dyn;                 // 3 * 64 * 64
    float* sIn = s_dyn + 3 * 4096;      // 64 * INPAD
    __shared__ float sX[NPB * 3];
    int tid = threadIdx.x;
    int nbase = gblk * NPB;

    for (int i = tid * 4; i < 4096; i += 1024) {
        *(float4*)&sW[i]        = *(const float4*)&W0[i];
        *(float4*)&sW[4096 + i] = *(const float4*)&W1[i];
        *(float4*)&sW[8192 + i] = *(const float4*)&W2[i];
    }

    if (mode == 0) {
        if (tid < NPB * 3) {
            int nd = tid / 3, c = tid % 3;
            int node = nbase + nd;
            sX[tid] = (node < NN) ? __ldg(&in[node * 3 + c]) : 0.f;
        }
        __syncthreads();
        for (int i = tid; i < NPB * 64; i += 256) {
            int nd = i >> 6, k = i & 63;
            float v = fmaf(sX[nd * 3 + 0], __ldg(&Wn[k]),
                      fmaf(sX[nd * 3 + 1], __ldg(&Wn[64 + k]),
                      fmaf(sX[nd * 3 + 2], __ldg(&Wn[128 + k]), __ldg(&bn[k]))));
            sIn[nd * INPAD + k] = fmaxf(v, 0.f);
        }
    } else {
        for (int i = tid * 4; i < NPB * 64; i += 1024) {
            int nd = i >> 6, k = i & 63;
            int node = nbase + nd;
            float4 v = make_float4(0.f, 0.f, 0.f, 0.f);
            if (node < NN) v = *(const float4*)&in[node * 64 + k];
            v.x = fmaxf(v.x, 0.f); v.y = fmaxf(v.y, 0.f);
            v.z = fmaxf(v.z, 0.f); v.w = fmaxf(v.w, 0.f);
            *(float4*)&sIn[nd * INPAD + k] = v;
        }
    }
    __syncthreads();

    int tx = tid & 15, ty = tid >> 4;
    int c0 = tx * 4, n0 = ty * 4;
    float acc[3][4][4] = {};

    #pragma unroll 2
    for (int k = 0; k < 64; k++) {
        float4 w0 = *(float4*)&sW[k * 64 + c0];
        float4 w1 = *(float4*)&sW[4096 + k * 64 + c0];
        float4 w2 = *(float4*)&sW[8192 + k * 64 + c0];
        float a[4];
        #pragma unroll
        for (int j = 0; j < 4; j++) a[j] = sIn[(n0 + j) * INPAD + k];
        #pragma unroll
        for (int j = 0; j < 4; j++) {
            acc[0][j][0] = fmaf(a[j], w0.x, acc[0][j][0]);
            acc[0][j][1] = fmaf(a[j], w0.y, acc[0][j][1]);
            acc[0][j][2] = fmaf(a[j], w0.z, acc[0][j][2]);
            acc[0][j][3] = fmaf(a[j], w0.w, acc[0][j][3]);
            acc[1][j][0] = fmaf(a[j], w1.x, acc[1][j][0]);
            acc[1][j][1] = fmaf(a[j], w1.y, acc[1][j][1]);
            acc[1][j][2] = fmaf(a[j], w1.z, acc[1][j][2]);
            acc[1][j][3] = fmaf(a[j], w1.w, acc[1][j][3]);
            acc[2][j][0] = fmaf(a[j], w2.x, acc[2][j][0]);
            acc[2][j][1] = fmaf(a[j], w2.y, acc[2][j][1]);
            acc[2][j][2] = fmaf(a[j], w2.z, acc[2][j][2]);
            acc[2][j][3] = fmaf(a[j], w2.w, acc[2][j][3]);
        }
    }

    float4 bv = *(const float4*)&bias2[c0];
    #pragma unroll
    for (int j = 0; j < 4; j++) {
        int node = nbase + n0 + j;
        if (node >= NN) break;
        *(float4*)&oAB[node * 128 + c0] =
            make_float4(acc[0][j][0], acc[0][j][1], acc[0][j][2], acc[0][j][3]);
        *(float4*)&oAB[node * 128 + 64 + c0] =
            make_float4(acc[1][j][0], acc[1][j][1], acc[1][j][2], acc[1][j][3]);
        *(float4*)&o2[node * 64 + c0] =
            make_float4(acc[2][j][0] + bv.x, acc[2][j][1] + bv.y,
                        acc[2][j][2] + bv.z, acc[2][j][3] + bv.w);
    }
}

// conv1 front: blocks [0, GEMM_GRID) gemm (mode 0); trailing blocks: degree hist.
__global__ __launch_bounds__(256)
void k_conv1_front(const float* __restrict__ x,
                   const float* __restrict__ W0,
                   const float* __restrict__ W1,
                   const float* __restrict__ W2,
                   const float* __restrict__ bias2,
                   const float* __restrict__ Wn,
                   const float* __restrict__ bn,
                   float* __restrict__ oAB,
                   float* __restrict__ o2,
                   const int* __restrict__ ei) {
    if (blockIdx.x < GEMM_GRID) {
        gemm_body(blockIdx.x, x, W0, W1, W2, bias2, Wn, bn, oAB, o2, 0);
    } else {
        int e = (blockIdx.x - GEMM_GRID) * blockDim.x + threadIdx.x;
        if (e < NE) atomicAdd(&g_deg[ei[NE + e]], 1);
    }
}

// conv2 node-side GEMM (mode 1)
__global__ __launch_bounds__(256)
void k_gemm3(const float* __restrict__ in,
             const float* __restrict__ W0,
             const float* __restrict__ W1,
             const float* __restrict__ W2,
             const float* __restrict__ bias2,
             float* __restrict__ oAB,
             float* __restrict__ o2) {
    gemm_body(blockIdx.x, in, W0, W1, W2, bias2, nullptr, nullptr, oAB, o2, 1);
}

// ---------------------------------------------------------------------------
// conv1 gather: one warp per dst node; EDGE-PAIRED float4 gathers.
// Lanes 0-15 gather edge e, lanes 16-31 edge e+1 (each lane: float4 = 4 cols).
// Halves merged once via shfl_xor(16). ea recovered from one half2 shuffle.
// ---------------------------------------------------------------------------
__global__ __launch_bounds__(256, 5)
void k_gather1(const float* __restrict__ We,
               const float* __restrict__ be,
               const float* __restrict__ W1e) {
    __shared__ float  sWe0[32], sWe1[32], sbe[32];
    __shared__ float4 sW1e[32 * 16];    // [k][colquad]
    int tid = threadIdx.x;
    if (tid < 32) { sWe0[tid] = We[tid]; sWe1[tid] = We[32 + tid]; sbe[tid] = be[tid]; }
    for (int i = tid; i < 512; i += blockDim.x)
        sW1e[i] = ((const float4*)W1e)[i];
    __syncthreads();

    int lane = tid & 31;
    int half = lane >> 4;
    int hl   = lane & 15;
    int node = (blockIdx.x * blockDim.x + tid) >> 5;
    if (node >= NN) return;
    int s0 = g_off[node], s1 = g_off[node + 1];
    const float4* mm4 = (const float4*)g_mm;

    float we0 = sWe0[lane], we1 = sWe1[lane], beL = sbe[lane];
    float  ev = 0.f;
    float4 ms = make_float4(0.f, 0.f, 0.f, 0.f);

    for (int base = s0; base < s1; base += 32) {
        int cnt = min(32, s1 - base);
        uint2 d = make_uint2(0u, 0u);
        if (base + lane < s1) d = __ldg(&g_csr_ed[base + lane]);

        int k = 0;
        for (; k + 8 <= cnt; k += 8) {
            unsigned o0 = __shfl_sync(FULL, d.x, k     + half);
            unsigned o1 = __shfl_sync(FULL, d.x, k + 2 + half);
            unsigned o2 = __shfl_sync(FULL, d.x, k + 4 + half);
            unsigned o3 = __shfl_sync(FULL, d.x, k + 6 + half);
            float4 v0 = __ldg(&mm4[o0 + hl]);
            float4 v1 = __ldg(&mm4[o1 + hl]);
            float4 v2 = __ldg(&mm4[o2 + hl]);
            float4 v3 = __ldg(&mm4[o3 + hl]);
            #pragma unroll
            for (int j = 0; j < 8; j++) {
                unsigned hu = __shfl_sync(FULL, d.y, k + j);
                float2 a = __half22float2(*reinterpret_cast<__half2*>(&hu));
                ev += fmaxf(fmaf(a.x, we0, fmaf(a.y, we1, beL)), 0.f);
            }
            ms.x += (v0.x + v1.x) + (v2.x + v3.x);
            ms.y += (v0.y + v1.y) + (v2.y + v3.y);
            ms.z += (v0.z + v1.z) + (v2.z + v3.z);
            ms.w += (v0.w + v1.w) + (v2.w + v3.w);
        }
        for (; k + 2 <= cnt; k += 2) {
            unsigned op = __shfl_sync(FULL, d.x, k + half);
            float4 v = __ldg(&mm4[op + hl]);
            unsigned h0 = __shfl_sync(FULL, d.y, k);
            unsigned h1 = __shfl_sync(FULL, d.y, k + 1);
            float2 a0 = __half22float2(*reinterpret_cast<__half2*>(&h0));
            float2 a1 = __half22float2(*reinterpret_cast<__half2*>(&h1));
            ev += fmaxf(fmaf(a0.x, we0, fmaf(a0.y, we1, beL)), 0.f);
            ev += fmaxf(fmaf(a1.x, we0, fmaf(a1.y, we1, beL)), 0.f);
            ms.x += v.x; ms.y += v.y; ms.z += v.z; ms.w += v.w;
        }
        if (k < cnt) {
            unsigned off = __shfl_sync(FULL, d.x, k);
            unsigned h0  = __shfl_sync(FULL, d.y, k);
            float2 a0 = __half22float2(*reinterpret_cast<__half2*>(&h0));
            ev += fmaxf(fmaf(a0.x, we0, fmaf(a0.y, we1, beL)), 0.f);
            if (half == 0) {
                float4 v = __ldg(&mm4[off + hl]);
                ms.x += v.x; ms.y += v.y; ms.z += v.z; ms.w += v.w;
            }
        }
    }

    // merge even/odd edge halves (each lane pair (l, l+16) owns same 4 cols)
    ms.x += __shfl_xor_sync(FULL, ms.x, 16);
    ms.y += __shfl_xor_sync(FULL, ms.y, 16);
    ms.z += __shfl_xor_sync(FULL, ms.z, 16);
    ms.w += __shfl_xor_sync(FULL, ms.w, 16);

    // aggev @ W1_edge  (ev dim k lives in lane k)
    float4 acc = make_float4(0.f, 0.f, 0.f, 0.f);
    #pragma unroll
    for (int k = 0; k < 32; k++) {
        float ek = __shfl_sync(FULL, ev, k);
        float4 w = sW1e[k * 16 + hl];
        acc.x = fmaf(ek, w.x, acc.x);
        acc.y = fmaf(ek, w.y, acc.y);
        acc.z = fmaf(ek, w.z, acc.z);
        acc.w = fmaf(ek, w.w, acc.w);
    }

    if (half == 0) {
        float4 r = *(const float4*)&g_r1[node * 64 + hl * 4];
        *(float4*)&g_hpre[node * 64 + hl * 4] =
            make_float4(r.x + ms.x + acc.x, r.y + ms.y + acc.y,
                        r.z + ms.z + acc.z, r.w + ms.w + acc.w);
    }
}

// ---------------------------------------------------------------------------
// conv2 gather + readout: one warp per dst node; edge-paired float4 gathers.
// ---------------------------------------------------------------------------
__global__ __launch_bounds__(256, 6)
void k_gather2(const float* __restrict__ Wc,
               const float* __restrict__ bc,
               float* __restrict__ out) {
    int tid  = threadIdx.x;
    int lane = tid & 31;
    int half = lane >> 4;
    int hl   = lane & 15;
    int node = (blockIdx.x * blockDim.x + tid) >> 5;
    if (node >= NN) return;
    int s0 = g_off[node], s1 = g_off[node + 1];
    const float4* pp4 = (const float4*)g_pp;

    float4 mx = make_float4(-CUDART_INF_F, -CUDART_INF_F, -CUDART_INF_F, -CUDART_INF_F);
    for (int base = s0; base < s1; base += 32) {
        int cnt = min(32, s1 - base);
        unsigned dx = 0u;
        if (base + lane < s1) dx = __ldg(&g_csr_ed[base + lane]).x;

        int k = 0;
        for (; k + 8 <= cnt; k += 8) {
            unsigned o0 = __shfl_sync(FULL, dx, k     + half);
            unsigned o1 = __shfl_sync(FULL, dx, k + 2 + half);
            unsigned o2 = __shfl_sync(FULL, dx, k + 4 + half);
            unsigned o3 = __shfl_sync(FULL, dx, k + 6 + half);
            float4 v0 = __ldg(&pp4[o0 + hl]);
            float4 v1 = __ldg(&pp4[o1 + hl]);
            float4 v2 = __ldg(&pp4[o2 + hl]);
            float4 v3 = __ldg(&pp4[o3 + hl]);
            mx.x = fmaxf(mx.x, fmaxf(fmaxf(v0.x, v1.x), fmaxf(v2.x, v3.x)));
            mx.y = fmaxf(mx.y, fmaxf(fmaxf(v0.y, v1.y), fmaxf(v2.y, v3.y)));
            mx.z = fmaxf(mx.z, fmaxf(fmaxf(v0.z, v1.z), fmaxf(v2.z, v3.z)));
            mx.w = fmaxf(mx.w, fmaxf(fmaxf(v0.w, v1.w), fmaxf(v2.w, v3.w)));
        }
        for (; k + 2 <= cnt; k += 2) {
            unsigned op = __shfl_sync(FULL, dx, k + half);
            float4 v = __ldg(&pp4[op + hl]);
            mx.x = fmaxf(mx.x, v.x); mx.y = fmaxf(mx.y, v.y);
            mx.z = fmaxf(mx.z, v.z); mx.w = fmaxf(mx.w, v.w);
        }
        if (k < cnt) {
            unsigned off = __shfl_sync(FULL, dx, k);
            if (half == 0) {
                float4 v = __ldg(&pp4[off + hl]);
                mx.x = fmaxf(mx.x, v.x); mx.y = fmaxf(mx.y, v.y);
                mx.z = fmaxf(mx.z, v.z); mx.w = fmaxf(mx.w, v.w);
            }
        }
    }
    // merge halves
    mx.x = fmaxf(mx.x, __shfl_xor_sync(FULL, mx.x, 16));
    mx.y = fmaxf(mx.y, __shfl_xor_sync(FULL, mx.y, 16));
    mx.z = fmaxf(mx.z, __shfl_xor_sync(FULL, mx.z, 16));
    mx.w = fmaxf(mx.w, __shfl_xor_sync(FULL, mx.w, 16));
    if (s1 == s0) mx = make_float4(0.f, 0.f, 0.f, 0.f);

    float4 r = *(const float4*)&g_r2[node * 64 + hl * 4];
    float4 wc = *(const float4*)&Wc[hl * 4];
    float h0 = fmaxf(mx.x + r.x, 0.f);
    float h1 = fmaxf(mx.y + r.y, 0.f);
    float h2 = fmaxf(mx.z + r.z, 0.f);
    float h3 = fmaxf(mx.w + r.w, 0.f);
    float p = fmaf(h0, wc.x, fmaf(h1, wc.y, fmaf(h2, wc.z, h3 * wc.w)));
    // reduce over the 16 lanes of each half (halves hold identical data)
    #pragma unroll
    for (int o = 8; o > 0; o >>= 1) p += __shfl_xor_sync(FULL, p, o);
    if (lane == 0) out[node] = tanhf(p + __ldg(bc)) * 5.0f;
}

// ---------------------------------------------------------------------------
// launch
// ---------------------------------------------------------------------------
extern "C" void kernel_launch(void* const* d_in, const int* in_sizes, int n_in,
                              void* d_out, int out_size) {
    const float* x      = (const float*)d_in[0];
    const int*   ei     = (const int*)  d_in[1];
    const float* ea     = (const float*)d_in[2];
    const int*   et     = (const int*)  d_in[3];
    const float* Wn     = (const float*)d_in[4];
    const float* bn     = (const float*)d_in[5];
    const float* We     = (const float*)d_in[6];
    const float* be     = (const float*)d_in[7];
    const float* W1_rel = (const float*)d_in[8];
    const float* W1_edge= (const float*)d_in[9];
    const float* W1_root= (const float*)d_in[10];
    const float* b1     = (const float*)d_in[11];
    const float* W2_rel = (const float*)d_in[12];
    const float* W2_root= (const float*)d_in[13];
    const float* b2     = (const float*)d_in[14];
    const float* Wc     = (const float*)d_in[15];
    const float* bc     = (const float*)d_in[16];
    float* out          = (float*)d_out;

    float *pmm, *ppp, *pr1, *phpre, *pr2;
    int* pdeg;
    cudaGetSymbolAddress((void**)&pmm,   g_mm);
    cudaGetSymbolAddress((void**)&ppp,   g_pp);
    cudaGetSymbolAddress((void**)&pr1,   g_r1);
    cudaGetSymbolAddress((void**)&phpre, g_hpre);
    cudaGetSymbolAddress((void**)&pr2,   g_r2);
    cudaGetSymbolAddress((void**)&pdeg,  g_deg);

    static const int SMEM = (3 * 4096 + NPB * INPAD) * sizeof(float);
    cudaFuncSetAttribute(k_conv1_front, cudaFuncAttributeMaxDynamicSharedMemorySize, SMEM);
    cudaFuncSetAttribute(k_gemm3,       cudaFuncAttributeMaxDynamicSharedMemorySize, SMEM);

    const int edgeBlocks     = (NE + 255) / 256;
    const int nodeWarpBlocks = (NN * 32 + 255) / 256;

    cudaMemsetAsync(pdeg, 0, NN * sizeof(int));

    // conv1 node-side GEMMs (embed fused) + degree histogram in tail blocks
    k_conv1_front<<<GEMM_GRID + edgeBlocks, 256, SMEM>>>(
        x, W1_rel, W1_rel + 4096, W1_root, b1, Wn, bn, pmm, pr1, ei);

    // CSR offsets + fill
    k_scan<<<1, 1024>>>();
    k_fill<<<edgeBlocks, 256>>>(ei, ea, et);

    // conv1 gather (sum) + edge-feature fold
    k_gather1<<<nodeWarpBlocks, 256>>>(We, be, W1_edge);

    // conv2 node-side: h = relu(hpre) fused; pp table + r2
    k_gemm3<<<GEMM_GRID, 256, SMEM>>>(phpre, W2_rel, W2_rel + 4096, W2_root, b2,
                                      ppp, pr2);

    // conv2 gather (max) + readout fused
    k_gather2<<<nodeWarpBlocks, 256>>>(Wc, bc, out);
}

// round 13
// speedup vs baseline: 1.1447x; 1.1447x over previous
#include <cuda_runtime.h>
#include <cuda_bf16.h>
#include <cuda_fp16.h>
#include <math_constants.h>

#define NN 50000
#define NE 800000
#define HID 64
#define FULL 0xffffffffu

// ---------------------------------------------------------------------------
// Scratch (device globals; allocation-free per harness rules)
// ---------------------------------------------------------------------------
// Interleaved relation tables: row = 128 floats = [m_rel0 (64) | m_rel1 (64)]
__device__ __align__(16) float    g_mm  [NN * 128];   // conv1: n @ W1_rel[r]
__device__ __align__(16) float    g_pp  [NN * 128];   // conv2: h @ W2_rel[r]
__device__ __align__(16) float    g_r1  [NN * HID];   // n @ W1_root + b1
__device__ __align__(16) float    g_hpre[NN * HID];   // pre-relu h
__device__ __align__(16) float    g_r2  [NN * HID];   // h @ W2_root + b2
// CSR by dst
__device__ int   g_deg[NN];
__device__ int   g_off[NN + 1];
__device__ int   g_cur[NN];
__device__ __align__(16) uint4 g_csr_ed[NE];  // {off(src*64+typ*32 f2-units), ea.x, ea.y, 0}

// ---------------------------------------------------------------------------
// Vectorized single-block scan
// ---------------------------------------------------------------------------
__global__ void k_scan() {
    __shared__ int warpsum[32];
    int tid  = threadIdx.x;
    int lane = tid & 31;
    int wid  = tid >> 5;
    int carry = 0;
    for (int base = 0; base < NN; base += 4096) {
        int i0 = base + tid * 4;
        int v[4];
        #pragma unroll
        for (int j = 0; j < 4; j++) v[j] = (i0 + j < NN) ? g_deg[i0 + j] : 0;
        int tsum = (v[0] + v[1]) + (v[2] + v[3]);
        int s = tsum;
        #pragma unroll
        for (int o = 1; o < 32; o <<= 1) {
            int t = __shfl_up_sync(FULL, s, o);
            if (lane >= o) s += t;
        }
        if (lane == 31) warpsum[wid] = s;
        __syncthreads();
        if (wid == 0) {
            int ws = warpsum[lane];
            #pragma unroll
            for (int o = 1; o < 32; o <<= 1) {
                int t = __shfl_up_sync(FULL, ws, o);
                if (lane >= o) ws += t;
            }
            warpsum[lane] = ws;
        }
        __syncthreads();
        int wpre = (wid > 0) ? warpsum[wid - 1] : 0;
        int run  = carry + wpre + s - tsum;
        #pragma unroll
        for (int j = 0; j < 4; j++) {
            if (i0 + j < NN) { g_off[i0 + j] = run; g_cur[i0 + j] = run; run += v[j]; }
        }
        int total = warpsum[31];
        __syncthreads();
        carry += total;
    }
    if (tid == 0) g_off[NN] = NE;
}

// ---------------------------------------------------------------------------
// CSR fill (round-7 proven): fp32 ea, offsets in float2 units
// ---------------------------------------------------------------------------
__global__ void k_fill(const int* __restrict__ ei,
                       const float* __restrict__ ea,
                       const int* __restrict__ et) {
    int e = blockIdx.x * blockDim.x + threadIdx.x;
    if (e >= NE) return;
    int dst = ei[NE + e];
    int pos = atomicAdd(&g_cur[dst], 1);
    unsigned off = (unsigned)ei[e] * 64u + (unsigned)et[e] * 32u;
    float2 a = ((const float2*)ea)[e];
    g_csr_ed[pos] = make_uint4(off, __float_as_uint(a.x), __float_as_uint(a.y), 0u);
}

// ---------------------------------------------------------------------------
// HMMA triple GEMM via mma.sync.m16n8k16 (valid on base sm_100 target).
// Block: 256 thr = 8 warps, 128 nodes (warp w owns rows w*16..w*16+15).
// A: fp16 input rows in SMEM (pitch 72 halves). B: three 64x64 weights as
// k-paired half2 tiles (sWp[kp][n], pitch 65). D: fp32 accum.
// mode 0: f(in)=relu(x@Wn+bn) fused; mode 1: f(in)=relu(in).
// ---------------------------------------------------------------------------
#define MBLK 128
#define GEMM_BLKS ((NN + MBLK - 1) / MBLK)   // 391
#define INP 72                                // sIn pitch in halves
#define WPP 65                                // sWp pitch in half2

__device__ __forceinline__ void mma16816(float* c, const unsigned* a,
                                         unsigned b0, unsigned b1) {
    asm volatile(
        "mma.sync.aligned.m16n8k16.row.col.f32.f16.f16.f32 "
        "{%0,%1,%2,%3}, {%4,%5,%6,%7}, {%8,%9}, {%0,%1,%2,%3};"
        : "+f"(c[0]), "+f"(c[1]), "+f"(c[2]), "+f"(c[3])
        : "r"(a[0]), "r"(a[1]), "r"(a[2]), "r"(a[3]), "r"(b0), "r"(b1));
}

__device__ __forceinline__ void gemm_hmma_body(
        int gblk,
        const float* __restrict__ in,
        const float* __restrict__ W0,
        const float* __restrict__ W1,
        const float* __restrict__ W2,
        const float* __restrict__ bias2,
        const float* __restrict__ Wn,
        const float* __restrict__ bn,
        float* __restrict__ oAB,     // interleaved table (stride 128)
        float* __restrict__ o2,      // dense (stride 64)
        int mode) {
    __shared__ __half   sIn[MBLK * INP];          // 18432 B
    __shared__ __half2  sWp[3][32 * WPP];         // 24960 B
    __shared__ float    sX[MBLK * 3];
    int tid = threadIdx.x;
    int nbase = gblk * MBLK;

    // --- stage weights: sWp[m][ (k/2)*WPP + n ] = {W[k][n], W[k+1][n]} ---
    __half* sWpH0 = (__half*)sWp[0];
    __half* sWpH1 = (__half*)sWp[1];
    __half* sWpH2 = (__half*)sWp[2];
    for (int idx = tid; idx < 4096; idx += 256) {
        int k = idx >> 6, n = idx & 63;
        int kp = k >> 1, klo = k & 1;
        int sidx = (kp * WPP + n) * 2 + klo;
        sWpH0[sidx] = __float2half(W0[idx]);
        sWpH1[sidx] = __float2half(W1[idx]);
        sWpH2[sidx] = __float2half(W2[idx]);
    }

    // --- stage input rows (fp16) ---
    if (mode == 0) {
        for (int i = tid; i < MBLK * 3; i += 256) {
            int nd = i / 3, c = i % 3;
            int node = nbase + nd;
            sX[i] = (node < NN) ? __ldg(&in[node * 3 + c]) : 0.f;
        }
        __syncthreads();
        for (int i = tid; i < MBLK * 64; i += 256) {
            int nd = i >> 6, k = i & 63;
            float v = fmaf(sX[nd * 3 + 0], __ldg(&Wn[k]),
                      fmaf(sX[nd * 3 + 1], __ldg(&Wn[64 + k]),
                      fmaf(sX[nd * 3 + 2], __ldg(&Wn[128 + k]), __ldg(&bn[k]))));
            sIn[nd * INP + k] = __float2half(fmaxf(v, 0.f));
        }
    } else {
        for (int i = tid * 4; i < MBLK * 64; i += 256 * 4) {
            int nd = i >> 6, k = i & 63;
            int node = nbase + nd;
            float4 v = make_float4(0.f, 0.f, 0.f, 0.f);
            if (node < NN) v = *(const float4*)&in[node * 64 + k];
            __half2 h01 = __floats2half2_rn(fmaxf(v.x, 0.f), fmaxf(v.y, 0.f));
            __half2 h23 = __floats2half2_rn(fmaxf(v.z, 0.f), fmaxf(v.w, 0.f));
            *(uint2*)&sIn[nd * INP + k] = make_uint2(*(unsigned*)&h01, *(unsigned*)&h23);
        }
    }
    __syncthreads();

    int wid  = tid >> 5;
    int lane = tid & 31;
    int grp  = lane >> 2;      // 0..7
    int t4   = lane & 3;       // 0..3
    int wbase = wid * 16;

    // --- A fragments for all 4 k-steps (16 regs) ---
    unsigned afr[4][4];
    #pragma unroll
    for (int kk = 0; kk < 4; kk++) {
        int col = kk * 16 + t4 * 2;
        afr[kk][0] = *(const unsigned*)&sIn[(wbase + grp)     * INP + col];
        afr[kk][1] = *(const unsigned*)&sIn[(wbase + grp + 8) * INP + col];
        afr[kk][2] = *(const unsigned*)&sIn[(wbase + grp)     * INP + col + 8];
        afr[kk][3] = *(const unsigned*)&sIn[(wbase + grp + 8) * INP + col + 8];
    }

    int node0 = nbase + wbase + grp;
    int node1 = node0 + 8;

    #pragma unroll
    for (int m = 0; m < 3; m++) {
        float acc[8][4];
        #pragma unroll
        for (int nt = 0; nt < 8; nt++)
            #pragma unroll
            for (int j = 0; j < 4; j++) acc[nt][j] = 0.f;

        const __half2* wp = sWp[m];
        #pragma unroll
        for (int kk = 0; kk < 4; kk++) {
            #pragma unroll
            for (int nt = 0; nt < 8; nt++) {
                int n_abs = nt * 8 + grp;
                unsigned b0 = *(const unsigned*)&wp[(kk * 8 + t4)     * WPP + n_abs];
                unsigned b1 = *(const unsigned*)&wp[(kk * 8 + t4 + 4) * WPP + n_abs];
                mma16816(acc[nt], afr[kk], b0, b1);
            }
        }

        // epilogue
        if (m < 2) {
            #pragma unroll
            for (int nt = 0; nt < 8; nt++) {
                int c0 = nt * 8 + t4 * 2;
                if (node0 < NN)
                    *(float2*)&oAB[node0 * 128 + m * 64 + c0] =
                        make_float2(acc[nt][0], acc[nt][1]);
                if (node1 < NN)
                    *(float2*)&oAB[node1 * 128 + m * 64 + c0] =
                        make_float2(acc[nt][2], acc[nt][3]);
            }
        } else {
            #pragma unroll
            for (int nt = 0; nt < 8; nt++) {
                int c0 = nt * 8 + t4 * 2;
                float bx = __ldg(&bias2[c0]);
                float by = __ldg(&bias2[c0 + 1]);
                if (node0 < NN)
                    *(float2*)&o2[node0 * 64 + c0] =
                        make_float2(acc[nt][0] + bx, acc[nt][1] + by);
                if (node1 < NN)
                    *(float2*)&o2[node1 * 64 + c0] =
                        make_float2(acc[nt][2] + bx, acc[nt][3] + by);
            }
        }
    }
}

// conv1 front: blocks [0, GEMM_BLKS) gemm (mode 0); tail: degree hist.
__global__ __launch_bounds__(256)
void k_conv1_front(const float* __restrict__ x,
                   const float* __restrict__ W0,
                   const float* __restrict__ W1,
                   const float* __restrict__ W2,
                   const float* __restrict__ bias2,
                   const float* __restrict__ Wn,
                   const float* __restrict__ bn,
                   float* __restrict__ oAB,
                   float* __restrict__ o2,
                   const int* __restrict__ ei) {
    if (blockIdx.x >= GEMM_BLKS) {
        int e = (blockIdx.x - GEMM_BLKS) * blockDim.x + threadIdx.x;
        if (e < NE) atomicAdd(&g_deg[ei[NE + e]], 1);
        return;
    }
    gemm_hmma_body(blockIdx.x, x, W0, W1, W2, bias2, Wn, bn, oAB, o2, 0);
}

// conv2 gemm (mode 1)
__global__ __launch_bounds__(256)
void k_gemm3(const float* __restrict__ in,
             const float* __restrict__ W0,
             const float* __restrict__ W1,
             const float* __restrict__ W2,
             const float* __restrict__ bias2,
             float* __restrict__ oAB,
             float* __restrict__ o2) {
    gemm_hmma_body(blockIdx.x, in, W0, W1, W2, bias2, nullptr, nullptr, oAB, o2, 1);
}

// ---------------------------------------------------------------------------
// conv1 gather (round-7 proven): warp/node, staged records + shuffle broadcast
// ---------------------------------------------------------------------------
__global__ __launch_bounds__(256, 6)
void k_gather1(const float* __restrict__ We,
               const float* __restrict__ be,
               const float* __restrict__ W1e) {
    __shared__ float  sWe0[32], sWe1[32], sbe[32];
    __shared__ float2 sW1e[32 * 32];
    int tid = threadIdx.x;
    if (tid < 32) { sWe0[tid] = We[tid]; sWe1[tid] = We[32 + tid]; sbe[tid] = be[tid]; }
    for (int i = tid; i < 1024; i += blockDim.x)
        sW1e[i] = ((const float2*)W1e)[i];
    __syncthreads();

    int lane = tid & 31;
    int node = (blockIdx.x * blockDim.x + tid) >> 5;
    if (node >= NN) return;
    int s0 = g_off[node], s1 = g_off[node + 1];
    const float2* mm2 = (const float2*)g_mm;

    float we0 = sWe0[lane], we1 = sWe1[lane], beL = sbe[lane];
    float  ev = 0.f;
    float2 ms = make_float2(0.f, 0.f);

    for (int base = s0; base < s1; base += 32) {
        int cnt = min(32, s1 - base);
        uint4 d = make_uint4(0u, 0u, 0u, 0u);
        if (base + lane < s1) d = __ldg(&g_csr_ed[base + lane]);

        int k = 0;
        for (; k + 4 <= cnt; k += 4) {
            unsigned o0 = __shfl_sync(FULL, d.x, k);
            unsigned o1 = __shfl_sync(FULL, d.x, k + 1);
            unsigned o2 = __shfl_sync(FULL, d.x, k + 2);
            unsigned o3 = __shfl_sync(FULL, d.x, k + 3);
            float2 v0 = __ldg(&mm2[o0 + lane]);
            float2 v1 = __ldg(&mm2[o1 + lane]);
            float2 v2 = __ldg(&mm2[o2 + lane]);
            float2 v3 = __ldg(&mm2[o3 + lane]);
            float a0x = __uint_as_float(__shfl_sync(FULL, d.y, k));
            float a0y = __uint_as_float(__shfl_sync(FULL, d.z, k));
            float a1x = __uint_as_float(__shfl_sync(FULL, d.y, k + 1));
            float a1y = __uint_as_float(__shfl_sync(FULL, d.z, k + 1));
            float a2x = __uint_as_float(__shfl_sync(FULL, d.y, k + 2));
            float a2y = __uint_as_float(__shfl_sync(FULL, d.z, k + 2));
            float a3x = __uint_as_float(__shfl_sync(FULL, d.y, k + 3));
            float a3y = __uint_as_float(__shfl_sync(FULL, d.z, k + 3));
            ev += fmaxf(fmaf(a0x, we0, fmaf(a0y, we1, beL)), 0.f);
            ev += fmaxf(fmaf(a1x, we0, fmaf(a1y, we1, beL)), 0.f);
            ev += fmaxf(fmaf(a2x, we0, fmaf(a2y, we1, beL)), 0.f);
            ev += fmaxf(fmaf(a3x, we0, fmaf(a3y, we1, beL)), 0.f);
            ms.x += (v0.x + v1.x) + (v2.x + v3.x);
            ms.y += (v0.y + v1.y) + (v2.y + v3.y);
        }
        for (; k < cnt; k++) {
            unsigned off = __shfl_sync(FULL, d.x, k);
            float ax = __uint_as_float(__shfl_sync(FULL, d.y, k));
            float ay = __uint_as_float(__shfl_sync(FULL, d.z, k));
            float2 v = __ldg(&mm2[off + lane]);
            ev += fmaxf(fmaf(ax, we0, fmaf(ay, we1, beL)), 0.f);
            ms.x += v.x; ms.y += v.y;
        }
    }

    float2 acc = make_float2(0.f, 0.f);
    #pragma unroll
    for (int k = 0; k < 32; k++) {
        float ek = __shfl_sync(FULL, ev, k);
        float2 w = sW1e[k * 32 + lane];
        acc.x = fmaf(ek, w.x, acc.x);
        acc.y = fmaf(ek, w.y, acc.y);
    }
    float2 r = *(const float2*)&g_r1[node * 64 + 2 * lane];
    *(float2*)&g_hpre[node * 64 + 2 * lane] =
        make_float2(r.x + ms.x + acc.x, r.y + ms.y + acc.y);
}

// ---------------------------------------------------------------------------
// conv2 gather + readout (round-7 proven)
// ---------------------------------------------------------------------------
__global__ __launch_bounds__(256, 6)
void k_gather2(const float* __restrict__ Wc,
               const float* __restrict__ bc,
               float* __restrict__ out) {
    int tid  = threadIdx.x;
    int lane = tid & 31;
    int node = (blockIdx.x * blockDim.x + tid) >> 5;
    if (node >= NN) return;
    int s0 = g_off[node], s1 = g_off[node + 1];
    const float2* pp2 = (const float2*)g_pp;

    float2 mx = make_float2(-CUDART_INF_F, -CUDART_INF_F);
    for (int base = s0; base < s1; base += 32) {
        int cnt = min(32, s1 - base);
        unsigned dx = 0u;
        if (base + lane < s1) dx = __ldg(&g_csr_ed[base + lane]).x;

        int k = 0;
        for (; k + 4 <= cnt; k += 4) {
            unsigned o0 = __shfl_sync(FULL, dx, k);
            unsigned o1 = __shfl_sync(FULL, dx, k + 1);
            unsigned o2 = __shfl_sync(FULL, dx, k + 2);
            unsigned o3 = __shfl_sync(FULL, dx, k + 3);
            float2 v0 = __ldg(&pp2[o0 + lane]);
            float2 v1 = __ldg(&pp2[o1 + lane]);
            float2 v2 = __ldg(&pp2[o2 + lane]);
            float2 v3 = __ldg(&pp2[o3 + lane]);
            mx.x = fmaxf(mx.x, fmaxf(fmaxf(v0.x, v1.x), fmaxf(v2.x, v3.x)));
            mx.y = fmaxf(mx.y, fmaxf(fmaxf(v0.y, v1.y), fmaxf(v2.y, v3.y)));
        }
        for (; k < cnt; k++) {
            unsigned off = __shfl_sync(FULL, dx, k);
            float2 v = __ldg(&pp2[off + lane]);
            mx.x = fmaxf(mx.x, v.x);
            mx.y = fmaxf(mx.y, v.y);
        }
    }
    if (s1 == s0) mx = make_float2(0.f, 0.f);

    float2 r = *(const float2*)&g_r2[node * 64 + 2 * lane];
    float h0 = fmaxf(mx.x + r.x, 0.f);
    float h1 = fmaxf(mx.y + r.y, 0.f);
    float p = fmaf(h0, __ldg(&Wc[2 * lane]), h1 * __ldg(&Wc[2 * lane + 1]));
    #pragma unroll
    for (int o = 16; o > 0; o >>= 1) p += __shfl_xor_sync(FULL, p, o);
    if (lane == 0) out[node] = tanhf(p + __ldg(bc)) * 5.0f;
}

// ---------------------------------------------------------------------------
// launch
// ---------------------------------------------------------------------------
extern "C" void kernel_launch(void* const* d_in, const int* in_sizes, int n_in,
                              void* d_out, int out_size) {
    const float* x      = (const float*)d_in[0];
    const int*   ei     = (const int*)  d_in[1];
    const float* ea     = (const float*)d_in[2];
    const int*   et     = (const int*)  d_in[3];
    const float* Wn     = (const float*)d_in[4];
    const float* bn     = (const float*)d_in[5];
    const float* We     = (const float*)d_in[6];
    const float* be     = (const float*)d_in[7];
    const float* W1_rel = (const float*)d_in[8];
    const float* W1_edge= (const float*)d_in[9];
    const float* W1_root= (const float*)d_in[10];
    const float* b1     = (const float*)d_in[11];
    const float* W2_rel = (const float*)d_in[12];
    const float* W2_root= (const float*)d_in[13];
    const float* b2     = (const float*)d_in[14];
    const float* Wc     = (const float*)d_in[15];
    const float* bc     = (const float*)d_in[16];
    float* out          = (float*)d_out;

    float *pmm, *ppp, *pr1, *phpre, *pr2;
    int* pdeg;
    cudaGetSymbolAddress((void**)&pmm,   g_mm);
    cudaGetSymbolAddress((void**)&ppp,   g_pp);
    cudaGetSymbolAddress((void**)&pr1,   g_r1);
    cudaGetSymbolAddress((void**)&phpre, g_hpre);
    cudaGetSymbolAddress((void**)&pr2,   g_r2);
    cudaGetSymbolAddress((void**)&pdeg,  g_deg);

    const int histBlocks     = (NE + 255) / 256;
    const int edgeBlocks     = (NE + 255) / 256;
    const int nodeWarpBlocks = (NN * 32 + 255) / 256;

    cudaMemsetAsync(pdeg, 0, NN * sizeof(int));

    // conv1 node-side HMMA GEMMs (embed fused) + degree hist in tail blocks
    k_conv1_front<<<GEMM_BLKS + histBlocks, 256>>>(
        x, W1_rel, W1_rel + 4096, W1_root, b1, Wn, bn, pmm, pr1, ei);

    // CSR offsets + fill
    k_scan<<<1, 1024>>>();
    k_fill<<<edgeBlocks, 256>>>(ei, ea, et);

    // conv1 gather (sum) + edge-feature fold
    k_gather1<<<nodeWarpBlocks, 256>>>(We, be, W1_edge);

    // conv2 node-side HMMA GEMM: h = relu(hpre) fused
    k_gemm3<<<GEMM_BLKS, 256>>>(phpre, W2_rel, W2_rel + 4096, W2_root, b2,
                                ppp, pr2);

    // conv2 gather (max) + readout fused
    k_gather2<<<nodeWarpBlocks, 256>>>(Wc, bc, out);
}

// round 15
// speedup vs baseline: 1.1576x; 1.0112x over previous
#include <cuda_runtime.h>
#include <cuda_bf16.h>
#include <cuda_fp16.h>
#include <math_constants.h>

#define NN 50000
#define NE 800000
#define HID 64
#define FULL 0xffffffffu

// ---------------------------------------------------------------------------
// Scratch (device globals; allocation-free per harness rules)
// ---------------------------------------------------------------------------
// Interleaved relation tables in fp16: row = 128 halves = [m_rel0 | m_rel1]
__device__ __align__(16) __half   g_mm  [NN * 128];   // conv1: n @ W1_rel[r]
__device__ __align__(16) __half   g_pp  [NN * 128];   // conv2: h @ W2_rel[r]
__device__ __align__(16) float    g_r1  [NN * HID];   // n @ W1_root + b1  (fp32)
__device__ __align__(16) float    g_hpre[NN * HID];   // pre-relu h       (fp32)
__device__ __align__(16) float    g_r2  [NN * HID];   // h @ W2_root + b2 (fp32)
// CSR by dst
__device__ int      g_deg[NN];
__device__ int      g_off[NN + 1];
__device__ int      g_cur[NN];
__device__ __align__(16) uint4 g_csr_ed[NE];  // {off(src*64+typ*32 half2-units), ea.x, ea.y, 0}
__device__ unsigned g_csr_off[NE];            // compact offsets for gather2

// ---------------------------------------------------------------------------
// Vectorized single-block scan
// ---------------------------------------------------------------------------
__global__ void k_scan() {
    __shared__ int warpsum[32];
    int tid  = threadIdx.x;
    int lane = tid & 31;
    int wid  = tid >> 5;
    int carry = 0;
    for (int base = 0; base < NN; base += 4096) {
        int i0 = base + tid * 4;
        int v[4];
        #pragma unroll
        for (int j = 0; j < 4; j++) v[j] = (i0 + j < NN) ? g_deg[i0 + j] : 0;
        int tsum = (v[0] + v[1]) + (v[2] + v[3]);
        int s = tsum;
        #pragma unroll
        for (int o = 1; o < 32; o <<= 1) {
            int t = __shfl_up_sync(FULL, s, o);
            if (lane >= o) s += t;
        }
        if (lane == 31) warpsum[wid] = s;
        __syncthreads();
        if (wid == 0) {
            int ws = warpsum[lane];
            #pragma unroll
            for (int o = 1; o < 32; o <<= 1) {
                int t = __shfl_up_sync(FULL, ws, o);
                if (lane >= o) ws += t;
            }
            warpsum[lane] = ws;
        }
        __syncthreads();
        int wpre = (wid > 0) ? warpsum[wid - 1] : 0;
        int run  = carry + wpre + s - tsum;
        #pragma unroll
        for (int j = 0; j < 4; j++) {
            if (i0 + j < NN) { g_off[i0 + j] = run; g_cur[i0 + j] = run; run += v[j]; }
        }
        int total = warpsum[31];
        __syncthreads();
        carry += total;
    }
    if (tid == 0) g_off[NN] = NE;
}

// ---------------------------------------------------------------------------
// CSR fill: 16B record for gather1, compact 4B offset for gather2
// ---------------------------------------------------------------------------
__global__ void k_fill(const int* __restrict__ ei,
                       const float* __restrict__ ea,
                       const int* __restrict__ et) {
    int e = blockIdx.x * blockDim.x + threadIdx.x;
    if (e >= NE) return;
    int dst = ei[NE + e];
    int pos = atomicAdd(&g_cur[dst], 1);
    unsigned off = (unsigned)ei[e] * 64u + (unsigned)et[e] * 32u;  // half2 units
    float2 a = ((const float2*)ea)[e];
    g_csr_ed[pos]  = make_uint4(off, __float_as_uint(a.x), __float_as_uint(a.y), 0u);
    g_csr_off[pos] = off;
}

// ---------------------------------------------------------------------------
// HMMA triple GEMM via mma.sync.m16n8k16 (round-13 proven datapath).
// Relation outputs stored fp16 into the interleaved table; root output fp32.
// ---------------------------------------------------------------------------
#define MBLK 128
#define GEMM_BLKS ((NN + MBLK - 1) / MBLK)   // 391
#define INP 72                                // sIn pitch in halves
#define WPP 65                                // sWp pitch in half2

__device__ __forceinline__ void mma16816(float* c, const unsigned* a,
                                         unsigned b0, unsigned b1) {
    asm volatile(
        "mma.sync.aligned.m16n8k16.row.col.f32.f16.f16.f32 "
        "{%0,%1,%2,%3}, {%4,%5,%6,%7}, {%8,%9}, {%0,%1,%2,%3};"
        : "+f"(c[0]), "+f"(c[1]), "+f"(c[2]), "+f"(c[3])
        : "r"(a[0]), "r"(a[1]), "r"(a[2]), "r"(a[3]), "r"(b0), "r"(b1));
}

__device__ __forceinline__ void gemm_hmma_body(
        int gblk,
        const float* __restrict__ in,
        const float* __restrict__ W0,
        const float* __restrict__ W1,
        const float* __restrict__ W2,
        const float* __restrict__ bias2,
        const float* __restrict__ Wn,
        const float* __restrict__ bn,
        __half* __restrict__ oAB,    // interleaved fp16 table (stride 128 halves)
        float* __restrict__ o2,      // dense fp32 (stride 64)
        int mode) {
    __shared__ __half   sIn[MBLK * INP];          // 18432 B
    __shared__ __half2  sWp[3][32 * WPP];         // 24960 B
    __shared__ float    sX[MBLK * 3];
    int tid = threadIdx.x;
    int nbase = gblk * MBLK;

    // --- stage weights: sWp[m][ (k/2)*WPP + n ] = {W[k][n], W[k+1][n]} ---
    __half* sWpH0 = (__half*)sWp[0];
    __half* sWpH1 = (__half*)sWp[1];
    __half* sWpH2 = (__half*)sWp[2];
    for (int idx = tid; idx < 4096; idx += 256) {
        int k = idx >> 6, n = idx & 63;
        int kp = k >> 1, klo = k & 1;
        int sidx = (kp * WPP + n) * 2 + klo;
        sWpH0[sidx] = __float2half(W0[idx]);
        sWpH1[sidx] = __float2half(W1[idx]);
        sWpH2[sidx] = __float2half(W2[idx]);
    }

    // --- stage input rows (fp16) ---
    if (mode == 0) {
        for (int i = tid; i < MBLK * 3; i += 256) {
            int nd = i / 3, c = i % 3;
            int node = nbase + nd;
            sX[i] = (node < NN) ? __ldg(&in[node * 3 + c]) : 0.f;
        }
        __syncthreads();
        for (int i = tid; i < MBLK * 64; i += 256) {
            int nd = i >> 6, k = i & 63;
            float v = fmaf(sX[nd * 3 + 0], __ldg(&Wn[k]),
                      fmaf(sX[nd * 3 + 1], __ldg(&Wn[64 + k]),
                      fmaf(sX[nd * 3 + 2], __ldg(&Wn[128 + k]), __ldg(&bn[k]))));
            sIn[nd * INP + k] = __float2half(fmaxf(v, 0.f));
        }
    } else {
        for (int i = tid * 4; i < MBLK * 64; i += 256 * 4) {
            int nd = i >> 6, k = i & 63;
            int node = nbase + nd;
            float4 v = make_float4(0.f, 0.f, 0.f, 0.f);
            if (node < NN) v = *(const float4*)&in[node * 64 + k];
            __half2 h01 = __floats2half2_rn(fmaxf(v.x, 0.f), fmaxf(v.y, 0.f));
            __half2 h23 = __floats2half2_rn(fmaxf(v.z, 0.f), fmaxf(v.w, 0.f));
            *(uint2*)&sIn[nd * INP + k] = make_uint2(*(unsigned*)&h01, *(unsigned*)&h23);
        }
    }
    __syncthreads();

    int wid  = tid >> 5;
    int lane = tid & 31;
    int grp  = lane >> 2;      // 0..7
    int t4   = lane & 3;       // 0..3
    int wbase = wid * 16;

    // --- A fragments for all 4 k-steps ---
    unsigned afr[4][4];
    #pragma unroll
    for (int kk = 0; kk < 4; kk++) {
        int col = kk * 16 + t4 * 2;
        afr[kk][0] = *(const unsigned*)&sIn[(wbase + grp)     * INP + col];
        afr[kk][1] = *(const unsigned*)&sIn[(wbase + grp + 8) * INP + col];
        afr[kk][2] = *(const unsigned*)&sIn[(wbase + grp)     * INP + col + 8];
        afr[kk][3] = *(const unsigned*)&sIn[(wbase + grp + 8) * INP + col + 8];
    }

    int node0 = nbase + wbase + grp;
    int node1 = node0 + 8;

    #pragma unroll
    for (int m = 0; m < 3; m++) {
        float acc[8][4];
        #pragma unroll
        for (int nt = 0; nt < 8; nt++)
            #pragma unroll
            for (int j = 0; j < 4; j++) acc[nt][j] = 0.f;

        const __half2* wp = sWp[m];
        #pragma unroll
        for (int kk = 0; kk < 4; kk++) {
            #pragma unroll
            for (int nt = 0; nt < 8; nt++) {
                int n_abs = nt * 8 + grp;
                unsigned b0 = *(const unsigned*)&wp[(kk * 8 + t4)     * WPP + n_abs];
                unsigned b1 = *(const unsigned*)&wp[(kk * 8 + t4 + 4) * WPP + n_abs];
                mma16816(acc[nt], afr[kk], b0, b1);
            }
        }

        // epilogue
        if (m < 2) {
            #pragma unroll
            for (int nt = 0; nt < 8; nt++) {
                int c0 = nt * 8 + t4 * 2;
                if (node0 < NN)
                    *(__half2*)&oAB[node0 * 128 + m * 64 + c0] =
                        __floats2half2_rn(acc[nt][0], acc[nt][1]);
                if (node1 < NN)
                    *(__half2*)&oAB[node1 * 128 + m * 64 + c0] =
                        __floats2half2_rn(acc[nt][2], acc[nt][3]);
            }
        } else {
            #pragma unroll
            for (int nt = 0; nt < 8; nt++) {
                int c0 = nt * 8 + t4 * 2;
                float bx = __ldg(&bias2[c0]);
                float by = __ldg(&bias2[c0 + 1]);
                if (node0 < NN)
                    *(float2*)&o2[node0 * 64 + c0] =
                        make_float2(acc[nt][0] + bx, acc[nt][1] + by);
                if (node1 < NN)
                    *(float2*)&o2[node1 * 64 + c0] =
                        make_float2(acc[nt][2] + bx, acc[nt][3] + by);
            }
        }
    }
}

// conv1 front: blocks [0, GEMM_BLKS) gemm (mode 0); tail: degree hist.
__global__ __launch_bounds__(256)
void k_conv1_front(const float* __restrict__ x,
                   const float* __restrict__ W0,
                   const float* __restrict__ W1,
                   const float* __restrict__ W2,
                   const float* __restrict__ bias2,
                   const float* __restrict__ Wn,
                   const float* __restrict__ bn,
                   __half* __restrict__ oAB,
                   float* __restrict__ o2,
                   const int* __restrict__ ei) {
    if (blockIdx.x >= GEMM_BLKS) {
        int e = (blockIdx.x - GEMM_BLKS) * blockDim.x + threadIdx.x;
        if (e < NE) atomicAdd(&g_deg[ei[NE + e]], 1);
        return;
    }
    gemm_hmma_body(blockIdx.x, x, W0, W1, W2, bias2, Wn, bn, oAB, o2, 0);
}

// conv2 gemm (mode 1)
__global__ __launch_bounds__(256)
void k_gemm3(const float* __restrict__ in,
             const float* __restrict__ W0,
             const float* __restrict__ W1,
             const float* __restrict__ W2,
             const float* __restrict__ bias2,
             __half* __restrict__ oAB,
             float* __restrict__ o2) {
    gemm_hmma_body(blockIdx.x, in, W0, W1, W2, bias2, nullptr, nullptr, oAB, o2, 1);
}

// ---------------------------------------------------------------------------
// conv1 gather: warp/node, staged records + shuffle broadcast; fp16 row gather
// (one __half2 per lane = 1 L1 wavefront per row), fp32 accumulation.
// ---------------------------------------------------------------------------
__global__ __launch_bounds__(256, 6)
void k_gather1(const float* __restrict__ We,
               const float* __restrict__ be,
               const float* __restrict__ W1e) {
    __shared__ float  sWe0[32], sWe1[32], sbe[32];
    __shared__ float2 sW1e[32 * 32];
    int tid = threadIdx.x;
    if (tid < 32) { sWe0[tid] = We[tid]; sWe1[tid] = We[32 + tid]; sbe[tid] = be[tid]; }
    for (int i = tid; i < 1024; i += blockDim.x)
        sW1e[i] = ((const float2*)W1e)[i];
    __syncthreads();

    int lane = tid & 31;
    int node = (blockIdx.x * blockDim.x + tid) >> 5;
    if (node >= NN) return;
    int s0 = g_off[node], s1 = g_off[node + 1];
    const __half2* mm2 = (const __half2*)g_mm;

    float we0 = sWe0[lane], we1 = sWe1[lane], beL = sbe[lane];
    float  ev = 0.f;
    float2 ms = make_float2(0.f, 0.f);

    for (int base = s0; base < s1; base += 32) {
        int cnt = min(32, s1 - base);
        uint4 d = make_uint4(0u, 0u, 0u, 0u);
        if (base + lane < s1) d = __ldg(&g_csr_ed[base + lane]);

        int k = 0;
        for (; k + 4 <= cnt; k += 4) {
            unsigned o0 = __shfl_sync(FULL, d.x, k);
            unsigned o1 = __shfl_sync(FULL, d.x, k + 1);
            unsigned o2 = __shfl_sync(FULL, d.x, k + 2);
            unsigned o3 = __shfl_sync(FULL, d.x, k + 3);
            float2 v0 = __half22float2(__ldg(&mm2[o0 + lane]));
            float2 v1 = __half22float2(__ldg(&mm2[o1 + lane]));
            float2 v2 = __half22float2(__ldg(&mm2[o2 + lane]));
            float2 v3 = __half22float2(__ldg(&mm2[o3 + lane]));
            float a0x = __uint_as_float(__shfl_sync(FULL, d.y, k));
            float a0y = __uint_as_float(__shfl_sync(FULL, d.z, k));
            float a1x = __uint_as_float(__shfl_sync(FULL, d.y, k + 1));
            float a1y = __uint_as_float(__shfl_sync(FULL, d.z, k + 1));
            float a2x = __uint_as_float(__shfl_sync(FULL, d.y, k + 2));
            float a2y = __uint_as_float(__shfl_sync(FULL, d.z, k + 2));
            float a3x = __uint_as_float(__shfl_sync(FULL, d.y, k + 3));
            float a3y = __uint_as_float(__shfl_sync(FULL, d.z, k + 3));
            ev += fmaxf(fmaf(a0x, we0, fmaf(a0y, we1, beL)), 0.f);
            ev += fmaxf(fmaf(a1x, we0, fmaf(a1y, we1, beL)), 0.f);
            ev += fmaxf(fmaf(a2x, we0, fmaf(a2y, we1, beL)), 0.f);
            ev += fmaxf(fmaf(a3x, we0, fmaf(a3y, we1, beL)), 0.f);
            ms.x += (v0.x + v1.x) + (v2.x + v3.x);
            ms.y += (v0.y + v1.y) + (v2.y + v3.y);
        }
        for (; k < cnt; k++) {
            unsigned off = __shfl_sync(FULL, d.x, k);
            float ax = __uint_as_float(__shfl_sync(FULL, d.y, k));
            float ay = __uint_as_float(__shfl_sync(FULL, d.z, k));
            float2 v = __half22float2(__ldg(&mm2[off + lane]));
            ev += fmaxf(fmaf(ax, we0, fmaf(ay, we1, beL)), 0.f);
            ms.x += v.x; ms.y += v.y;
        }
    }

    float2 acc = make_float2(0.f, 0.f);
    #pragma unroll
    for (int k = 0; k < 32; k++) {
        float ek = __shfl_sync(FULL, ev, k);
        float2 w = sW1e[k * 32 + lane];
        acc.x = fmaf(ek, w.x, acc.x);
        acc.y = fmaf(ek, w.y, acc.y);
    }
    float2 r = *(const float2*)&g_r1[node * 64 + 2 * lane];
    *(float2*)&g_hpre[node * 64 + 2 * lane] =
        make_float2(r.x + ms.x + acc.x, r.y + ms.y + acc.y);
}

// ---------------------------------------------------------------------------
// conv2 gather + readout: compact 4B CSR offsets, fp16 row gather, __hmax2.
// ---------------------------------------------------------------------------
__global__ __launch_bounds__(256, 6)
void k_gather2(const float* __restrict__ Wc,
               const float* __restrict__ bc,
               float* __restrict__ out) {
    int tid  = threadIdx.x;
    int lane = tid & 31;
    int node = (blockIdx.x * blockDim.x + tid) >> 5;
    if (node >= NN) return;
    int s0 = g_off[node], s1 = g_off[node + 1];
    const __half2* pp2 = (const __half2*)g_pp;

    __half2 mxh = __half2half2(__float2half(-CUDART_INF_F));
    for (int base = s0; base < s1; base += 32) {
        int cnt = min(32, s1 - base);
        unsigned dx = 0u;
        if (base + lane < s1) dx = __ldg(&g_csr_off[base + lane]);

        int k = 0;
        for (; k + 4 <= cnt; k += 4) {
            unsigned o0 = __shfl_sync(FULL, dx, k);
            unsigned o1 = __shfl_sync(FULL, dx, k + 1);
            unsigned o2 = __shfl_sync(FULL, dx, k + 2);
            unsigned o3 = __shfl_sync(FULL, dx, k + 3);
            __half2 v0 = __ldg(&pp2[o0 + lane]);
            __half2 v1 = __ldg(&pp2[o1 + lane]);
            __half2 v2 = __ldg(&pp2[o2 + lane]);
            __half2 v3 = __ldg(&pp2[o3 + lane]);
            mxh = __hmax2(mxh, __hmax2(__hmax2(v0, v1), __hmax2(v2, v3)));
        }
        for (; k < cnt; k++) {
            unsigned off = __shfl_sync(FULL, dx, k);
            mxh = __hmax2(mxh, __ldg(&pp2[off + lane]));
        }
    }
    float2 mx = __half22float2(mxh);
    if (s1 == s0) mx = make_float2(0.f, 0.f);

    float2 r = *(const float2*)&g_r2[node * 64 + 2 * lane];
    float h0 = fmaxf(mx.x + r.x, 0.f);
    float h1 = fmaxf(mx.y + r.y, 0.f);
    float p = fmaf(h0, __ldg(&Wc[2 * lane]), h1 * __ldg(&Wc[2 * lane + 1]));
    #pragma unroll
    for (int o = 16; o > 0; o >>= 1) p += __shfl_xor_sync(FULL, p, o);
    if (lane == 0) out[node] = tanhf(p + __ldg(bc)) * 5.0f;
}

// ---------------------------------------------------------------------------
// launch
// ---------------------------------------------------------------------------
extern "C" void kernel_launch(void* const* d_in, const int* in_sizes, int n_in,
                              void* d_out, int out_size) {
    const float* x      = (const float*)d_in[0];
    const int*   ei     = (const int*)  d_in[1];
    const float* ea     = (const float*)d_in[2];
    const int*   et     = (const int*)  d_in[3];
    const float* Wn     = (const float*)d_in[4];
    const float* bn     = (const float*)d_in[5];
    const float* We     = (const float*)d_in[6];
    const float* be     = (const float*)d_in[7];
    const float* W1_rel = (const float*)d_in[8];
    const float* W1_edge= (const float*)d_in[9];
    const float* W1_root= (const float*)d_in[10];
    const float* b1     = (const float*)d_in[11];
    const float* W2_rel = (const float*)d_in[12];
    const float* W2_root= (const float*)d_in[13];
    const float* b2     = (const float*)d_in[14];
    const float* Wc     = (const float*)d_in[15];
    const float* bc     = (const float*)d_in[16];
    float* out          = (float*)d_out;

    __half *pmm, *ppp;
    float *pr1, *phpre, *pr2;
    int* pdeg;
    cudaGetSymbolAddress((void**)&pmm,   g_mm);
    cudaGetSymbolAddress((void**)&ppp,   g_pp);
    cudaGetSymbolAddress((void**)&pr1,   g_r1);
    cudaGetSymbolAddress((void**)&phpre, g_hpre);
    cudaGetSymbolAddress((void**)&pr2,   g_r2);
    cudaGetSymbolAddress((void**)&pdeg,  g_deg);

    const int histBlocks     = (NE + 255) / 256;
    const int edgeBlocks     = (NE + 255) / 256;
    const int nodeWarpBlocks = (NN * 32 + 255) / 256;

    cudaMemsetAsync(pdeg, 0, NN * sizeof(int));

    // conv1 node-side HMMA GEMMs (embed fused) + degree hist in tail blocks
    k_conv1_front<<<GEMM_BLKS + histBlocks, 256>>>(
        x, W1_rel, W1_rel + 4096, W1_root, b1, Wn, bn, pmm, pr1, ei);

    // CSR offsets + fill
    k_scan<<<1, 1024>>>();
    k_fill<<<edgeBlocks, 256>>>(ei, ea, et);

    // conv1 gather (sum) + edge-feature fold
    k_gather1<<<nodeWarpBlocks, 256>>>(We, be, W1_edge);

    // conv2 node-side HMMA GEMM: h = relu(hpre) fused
    k_gemm3<<<GEMM_BLKS, 256>>>(phpre, W2_rel, W2_rel + 4096, W2_root, b2,
                                ppp, pr2);

    // conv2 gather (max) + readout fused
    k_gather2<<<nodeWarpBlocks, 256>>>(Wc, bc, out);
}

// round 17
// speedup vs baseline: 1.1844x; 1.0232x over previous
#include <cuda_runtime.h>
#include <cuda_bf16.h>
#include <cuda_fp16.h>
#include <math_constants.h>

#define NN 50000
#define NE 800000
#define HID 64
#define FULL 0xffffffffu

// ---------------------------------------------------------------------------
// Scratch (device globals; allocation-free per harness rules)
// ---------------------------------------------------------------------------
// Interleaved relation tables in fp16: row = 128 halves = [m_rel0 | m_rel1]
__device__ __align__(16) __half   g_mm  [NN * 128];   // conv1: n @ W1_rel[r]
__device__ __align__(16) __half   g_pp  [NN * 128];   // conv2: h @ W2_rel[r]
__device__ __align__(16) float    g_r1  [NN * HID];   // n @ W1_root + b1  (fp32)
__device__ __align__(16) float    g_hpre[NN * HID];   // pre-relu h       (fp32)
__device__ __align__(16) float    g_r2  [NN * HID];   // h @ W2_root + b2 (fp32)
// CSR by dst
__device__ int      g_deg[NN];
__device__ int      g_off[NN + 1];
__device__ int      g_cur[NN];
__device__ __align__(8) uint2 g_csr_ed[NE];   // {off(src*64+typ*32 half2-units), half2(ea)}
__device__ unsigned g_csr_off[NE];            // compact offsets for gather2

// ---------------------------------------------------------------------------
// Vectorized single-block scan
// ---------------------------------------------------------------------------
__global__ void k_scan() {
    __shared__ int warpsum[32];
    int tid  = threadIdx.x;
    int lane = tid & 31;
    int wid  = tid >> 5;
    int carry = 0;
    for (int base = 0; base < NN; base += 4096) {
        int i0 = base + tid * 4;
        int v[4];
        #pragma unroll
        for (int j = 0; j < 4; j++) v[j] = (i0 + j < NN) ? g_deg[i0 + j] : 0;
        int tsum = (v[0] + v[1]) + (v[2] + v[3]);
        int s = tsum;
        #pragma unroll
        for (int o = 1; o < 32; o <<= 1) {
            int t = __shfl_up_sync(FULL, s, o);
            if (lane >= o) s += t;
        }
        if (lane == 31) warpsum[wid] = s;
        __syncthreads();
        if (wid == 0) {
            int ws = warpsum[lane];
            #pragma unroll
            for (int o = 1; o < 32; o <<= 1) {
                int t = __shfl_up_sync(FULL, ws, o);
                if (lane >= o) ws += t;
            }
            warpsum[lane] = ws;
        }
        __syncthreads();
        int wpre = (wid > 0) ? warpsum[wid - 1] : 0;
        int run  = carry + wpre + s - tsum;
        #pragma unroll
        for (int j = 0; j < 4; j++) {
            if (i0 + j < NN) { g_off[i0 + j] = run; g_cur[i0 + j] = run; run += v[j]; }
        }
        int total = warpsum[31];
        __syncthreads();
        carry += total;
    }
    if (tid == 0) g_off[NN] = NE;
}

// ---------------------------------------------------------------------------
// CSR fill: 8B record {off, half2(ea)} for gather1, 4B offset for gather2
// ---------------------------------------------------------------------------
__global__ void k_fill(const int* __restrict__ ei,
                       const float* __restrict__ ea,
                       const int* __restrict__ et) {
    int e = blockIdx.x * blockDim.x + threadIdx.x;
    if (e >= NE) return;
    int dst = ei[NE + e];
    int pos = atomicAdd(&g_cur[dst], 1);
    unsigned off = (unsigned)ei[e] * 64u + (unsigned)et[e] * 32u;  // half2 units
    float2 a = ((const float2*)ea)[e];
    __half2 h = __floats2half2_rn(a.x, a.y);
    g_csr_ed[pos]  = make_uint2(off, *reinterpret_cast<unsigned*>(&h));
    g_csr_off[pos] = off;
}

// ---------------------------------------------------------------------------
// HMMA triple GEMM via mma.sync.m16n8k16 (round-13/15 proven datapath).
// Relation outputs stored fp16 into the interleaved table; root output fp32.
// ---------------------------------------------------------------------------
#define MBLK 128
#define GEMM_BLKS ((NN + MBLK - 1) / MBLK)   // 391
#define INP 72                                // sIn pitch in halves
#define WPP 65                                // sWp pitch in half2

__device__ __forceinline__ void mma16816(float* c, const unsigned* a,
                                         unsigned b0, unsigned b1) {
    asm volatile(
        "mma.sync.aligned.m16n8k16.row.col.f32.f16.f16.f32 "
        "{%0,%1,%2,%3}, {%4,%5,%6,%7}, {%8,%9}, {%0,%1,%2,%3};"
        : "+f"(c[0]), "+f"(c[1]), "+f"(c[2]), "+f"(c[3])
        : "r"(a[0]), "r"(a[1]), "r"(a[2]), "r"(a[3]), "r"(b0), "r"(b1));
}

__device__ __forceinline__ void gemm_hmma_body(
        int gblk,
        const float* __restrict__ in,
        const float* __restrict__ W0,
        const float* __restrict__ W1,
        const float* __restrict__ W2,
        const float* __restrict__ bias2,
        const float* __restrict__ Wn,
        const float* __restrict__ bn,
        __half* __restrict__ oAB,    // interleaved fp16 table (stride 128 halves)
        float* __restrict__ o2,      // dense fp32 (stride 64)
        int mode) {
    __shared__ __half   sIn[MBLK * INP];          // 18432 B
    __shared__ __half2  sWp[3][32 * WPP];         // 24960 B
    __shared__ float    sX[MBLK * 3];
    int tid = threadIdx.x;
    int nbase = gblk * MBLK;

    // --- stage weights: sWp[m][ (k/2)*WPP + n ] = {W[k][n], W[k+1][n]} ---
    __half* sWpH0 = (__half*)sWp[0];
    __half* sWpH1 = (__half*)sWp[1];
    __half* sWpH2 = (__half*)sWp[2];
    for (int idx = tid; idx < 4096; idx += 256) {
        int k = idx >> 6, n = idx & 63;
        int kp = k >> 1, klo = k & 1;
        int sidx = (kp * WPP + n) * 2 + klo;
        sWpH0[sidx] = __float2half(W0[idx]);
        sWpH1[sidx] = __float2half(W1[idx]);
        sWpH2[sidx] = __float2half(W2[idx]);
    }

    // --- stage input rows (fp16) ---
    if (mode == 0) {
        for (int i = tid; i < MBLK * 3; i += 256) {
            int nd = i / 3, c = i % 3;
            int node = nbase + nd;
            sX[i] = (node < NN) ? __ldg(&in[node * 3 + c]) : 0.f;
        }
        __syncthreads();
        for (int i = tid; i < MBLK * 64; i += 256) {
            int nd = i >> 6, k = i & 63;
            float v = fmaf(sX[nd * 3 + 0], __ldg(&Wn[k]),
                      fmaf(sX[nd * 3 + 1], __ldg(&Wn[64 + k]),
                      fmaf(sX[nd * 3 + 2], __ldg(&Wn[128 + k]), __ldg(&bn[k]))));
            sIn[nd * INP + k] = __float2half(fmaxf(v, 0.f));
        }
    } else {
        for (int i = tid * 4; i < MBLK * 64; i += 256 * 4) {
            int nd = i >> 6, k = i & 63;
            int node = nbase + nd;
            float4 v = make_float4(0.f, 0.f, 0.f, 0.f);
            if (node < NN) v = *(const float4*)&in[node * 64 + k];
            __half2 h01 = __floats2half2_rn(fmaxf(v.x, 0.f), fmaxf(v.y, 0.f));
            __half2 h23 = __floats2half2_rn(fmaxf(v.z, 0.f), fmaxf(v.w, 0.f));
            *(uint2*)&sIn[nd * INP + k] = make_uint2(*(unsigned*)&h01, *(unsigned*)&h23);
        }
    }
    __syncthreads();

    int wid  = tid >> 5;
    int lane = tid & 31;
    int grp  = lane >> 2;      // 0..7
    int t4   = lane & 3;       // 0..3
    int wbase = wid * 16;

    // --- A fragments for all 4 k-steps ---
    unsigned afr[4][4];
    #pragma unroll
    for (int kk = 0; kk < 4; kk++) {
        int col = kk * 16 + t4 * 2;
        afr[kk][0] = *(const unsigned*)&sIn[(wbase + grp)     * INP + col];
        afr[kk][1] = *(const unsigned*)&sIn[(wbase + grp + 8) * INP + col];
        afr[kk][2] = *(const unsigned*)&sIn[(wbase + grp)     * INP + col + 8];
        afr[kk][3] = *(const unsigned*)&sIn[(wbase + grp + 8) * INP + col + 8];
    }

    int node0 = nbase + wbase + grp;
    int node1 = node0 + 8;

    #pragma unroll
    for (int m = 0; m < 3; m++) {
        float acc[8][4];
        #pragma unroll
        for (int nt = 0; nt < 8; nt++)
            #pragma unroll
            for (int j = 0; j < 4; j++) acc[nt][j] = 0.f;

        const __half2* wp = sWp[m];
        #pragma unroll
        for (int kk = 0; kk < 4; kk++) {
            #pragma unroll
            for (int nt = 0; nt < 8; nt++) {
                int n_abs = nt * 8 + grp;
                unsigned b0 = *(const unsigned*)&wp[(kk * 8 + t4)     * WPP + n_abs];
                unsigned b1 = *(const unsigned*)&wp[(kk * 8 + t4 + 4) * WPP + n_abs];
                mma16816(acc[nt], afr[kk], b0, b1);
            }
        }

        // epilogue
        if (m < 2) {
            #pragma unroll
            for (int nt = 0; nt < 8; nt++) {
                int c0 = nt * 8 + t4 * 2;
                if (node0 < NN)
                    *(__half2*)&oAB[node0 * 128 + m * 64 + c0] =
                        __floats2half2_rn(acc[nt][0], acc[nt][1]);
                if (node1 < NN)
                    *(__half2*)&oAB[node1 * 128 + m * 64 + c0] =
                        __floats2half2_rn(acc[nt][2], acc[nt][3]);
            }
        } else {
            #pragma unroll
            for (int nt = 0; nt < 8; nt++) {
                int c0 = nt * 8 + t4 * 2;
                float bx = __ldg(&bias2[c0]);
                float by = __ldg(&bias2[c0 + 1]);
                if (node0 < NN)
                    *(float2*)&o2[node0 * 64 + c0] =
                        make_float2(acc[nt][0] + bx, acc[nt][1] + by);
                if (node1 < NN)
                    *(float2*)&o2[node1 * 64 + c0] =
                        make_float2(acc[nt][2] + bx, acc[nt][3] + by);
            }
        }
    }
}

// conv1 front: blocks [0, GEMM_BLKS) gemm (mode 0); tail: degree hist.
__global__ __launch_bounds__(256)
void k_conv1_front(const float* __restrict__ x,
                   const float* __restrict__ W0,
                   const float* __restrict__ W1,
                   const float* __restrict__ W2,
                   const float* __restrict__ bias2,
                   const float* __restrict__ Wn,
                   const float* __restrict__ bn,
                   __half* __restrict__ oAB,
                   float* __restrict__ o2,
                   const int* __restrict__ ei) {
    if (blockIdx.x >= GEMM_BLKS) {
        int e = (blockIdx.x - GEMM_BLKS) * blockDim.x + threadIdx.x;
        if (e < NE) atomicAdd(&g_deg[ei[NE + e]], 1);
        return;
    }
    gemm_hmma_body(blockIdx.x, x, W0, W1, W2, bias2, Wn, bn, oAB, o2, 0);
}

// conv2 gemm (mode 1)
__global__ __launch_bounds__(256)
void k_gemm3(const float* __restrict__ in,
             const float* __restrict__ W0,
             const float* __restrict__ W1,
             const float* __restrict__ W2,
             const float* __restrict__ bias2,
             __half* __restrict__ oAB,
             float* __restrict__ o2) {
    gemm_hmma_body(blockIdx.x, in, W0, W1, W2, bias2, nullptr, nullptr, oAB, o2, 1);
}

// ---------------------------------------------------------------------------
// conv1 gather: warp/node; 8B CSR records staged coalesced, 2 shuffles/edge
// (offset + packed fp16 ea); fp16 row gather; fp32 accumulation.
// ---------------------------------------------------------------------------
__global__ __launch_bounds__(256, 6)
void k_gather1(const float* __restrict__ We,
               const float* __restrict__ be,
               const float* __restrict__ W1e) {
    __shared__ float  sWe0[32], sWe1[32], sbe[32];
    __shared__ float2 sW1e[32 * 32];
    int tid = threadIdx.x;
    if (tid < 32) { sWe0[tid] = We[tid]; sWe1[tid] = We[32 + tid]; sbe[tid] = be[tid]; }
    for (int i = tid; i < 1024; i += blockDim.x)
        sW1e[i] = ((const float2*)W1e)[i];
    __syncthreads();

    int lane = tid & 31;
    int node = (blockIdx.x * blockDim.x + tid) >> 5;
    if (node >= NN) return;
    int s0 = g_off[node], s1 = g_off[node + 1];
    const __half2* mm2 = (const __half2*)g_mm;

    float we0 = sWe0[lane], we1 = sWe1[lane], beL = sbe[lane];
    float  ev = 0.f;
    float2 ms = make_float2(0.f, 0.f);

    for (int base = s0; base < s1; base += 32) {
        int cnt = min(32, s1 - base);
        uint2 d = make_uint2(0u, 0u);
        if (base + lane < s1) d = __ldg(&g_csr_ed[base + lane]);

        int k = 0;
        for (; k + 4 <= cnt; k += 4) {
            unsigned o0 = __shfl_sync(FULL, d.x, k);
            unsigned o1 = __shfl_sync(FULL, d.x, k + 1);
            unsigned o2 = __shfl_sync(FULL, d.x, k + 2);
            unsigned o3 = __shfl_sync(FULL, d.x, k + 3);
            unsigned e0 = __shfl_sync(FULL, d.y, k);
            unsigned e1 = __shfl_sync(FULL, d.y, k + 1);
            unsigned e2 = __shfl_sync(FULL, d.y, k + 2);
            unsigned e3 = __shfl_sync(FULL, d.y, k + 3);
            float2 v0 = __half22float2(__ldg(&mm2[o0 + lane]));
            float2 v1 = __half22float2(__ldg(&mm2[o1 + lane]));
            float2 v2 = __half22float2(__ldg(&mm2[o2 + lane]));
            float2 v3 = __half22float2(__ldg(&mm2[o3 + lane]));
            float2 a0 = __half22float2(*reinterpret_cast<__half2*>(&e0));
            float2 a1 = __half22float2(*reinterpret_cast<__half2*>(&e1));
            float2 a2 = __half22float2(*reinterpret_cast<__half2*>(&e2));
            float2 a3 = __half22float2(*reinterpret_cast<__half2*>(&e3));
            ev += fmaxf(fmaf(a0.x, we0, fmaf(a0.y, we1, beL)), 0.f);
            ev += fmaxf(fmaf(a1.x, we0, fmaf(a1.y, we1, beL)), 0.f);
            ev += fmaxf(fmaf(a2.x, we0, fmaf(a2.y, we1, beL)), 0.f);
            ev += fmaxf(fmaf(a3.x, we0, fmaf(a3.y, we1, beL)), 0.f);
            ms.x += (v0.x + v1.x) + (v2.x + v3.x);
            ms.y += (v0.y + v1.y) + (v2.y + v3.y);
        }
        for (; k < cnt; k++) {
            unsigned off = __shfl_sync(FULL, d.x, k);
            unsigned eh  = __shfl_sync(FULL, d.y, k);
            float2 v = __half22float2(__ldg(&mm2[off + lane]));
            float2 a = __half22float2(*reinterpret_cast<__half2*>(&eh));
            ev += fmaxf(fmaf(a.x, we0, fmaf(a.y, we1, beL)), 0.f);
            ms.x += v.x; ms.y += v.y;
        }
    }

    float2 acc = make_float2(0.f, 0.f);
    #pragma unroll
    for (int k = 0; k < 32; k++) {
        float ek = __shfl_sync(FULL, ev, k);
        float2 w = sW1e[k * 32 + lane];
        acc.x = fmaf(ek, w.x, acc.x);
        acc.y = fmaf(ek, w.y, acc.y);
    }
    float2 r = *(const float2*)&g_r1[node * 64 + 2 * lane];
    *(float2*)&g_hpre[node * 64 + 2 * lane] =
        make_float2(r.x + ms.x + acc.x, r.y + ms.y + acc.y);
}

// ---------------------------------------------------------------------------
// conv2 gather + readout: compact 4B CSR offsets, fp16 row gather, __hmax2.
// ---------------------------------------------------------------------------
__global__ __launch_bounds__(256, 6)
void k_gather2(const float* __restrict__ Wc,
               const float* __restrict__ bc,
               float* __restrict__ out) {
    int tid  = threadIdx.x;
    int lane = tid & 31;
    int node = (blockIdx.x * blockDim.x + tid) >> 5;
    if (node >= NN) return;
    int s0 = g_off[node], s1 = g_off[node + 1];
    const __half2* pp2 = (const __half2*)g_pp;

    __half2 mxh = __half2half2(__float2half(-CUDART_INF_F));
    for (int base = s0; base < s1; base += 32) {
        int cnt = min(32, s1 - base);
        unsigned dx = 0u;
        if (base + lane < s1) dx = __ldg(&g_csr_off[base + lane]);

        int k = 0;
        for (; k + 4 <= cnt; k += 4) {
            unsigned o0 = __shfl_sync(FULL, dx, k);
            unsigned o1 = __shfl_sync(FULL, dx, k + 1);
            unsigned o2 = __shfl_sync(FULL, dx, k + 2);
            unsigned o3 = __shfl_sync(FULL, dx, k + 3);
            __half2 v0 = __ldg(&pp2[o0 + lane]);
            __half2 v1 = __ldg(&pp2[o1 + lane]);
            __half2 v2 = __ldg(&pp2[o2 + lane]);
            __half2 v3 = __ldg(&pp2[o3 + lane]);
            mxh = __hmax2(mxh, __hmax2(__hmax2(v0, v1), __hmax2(v2, v3)));
        }
        for (; k < cnt; k++) {
            unsigned off = __shfl_sync(FULL, dx, k);
            mxh = __hmax2(mxh, __ldg(&pp2[off + lane]));
        }
    }
    float2 mx = __half22float2(mxh);
    if (s1 == s0) mx = make_float2(0.f, 0.f);

    float2 r = *(const float2*)&g_r2[node * 64 + 2 * lane];
    float h0 = fmaxf(mx.x + r.x, 0.f);
    float h1 = fmaxf(mx.y + r.y, 0.f);
    float p = fmaf(h0, __ldg(&Wc[2 * lane]), h1 * __ldg(&Wc[2 * lane + 1]));
    #pragma unroll
    for (int o = 16; o > 0; o >>= 1) p += __shfl_xor_sync(FULL, p, o);
    if (lane == 0) out[node] = tanhf(p + __ldg(bc)) * 5.0f;
}

// ---------------------------------------------------------------------------
// launch
// ---------------------------------------------------------------------------
extern "C" void kernel_launch(void* const* d_in, const int* in_sizes, int n_in,
                              void* d_out, int out_size) {
    const float* x      = (const float*)d_in[0];
    const int*   ei     = (const int*)  d_in[1];
    const float* ea     = (const float*)d_in[2];
    const int*   et     = (const int*)  d_in[3];
    const float* Wn     = (const float*)d_in[4];
    const float* bn     = (const float*)d_in[5];
    const float* We     = (const float*)d_in[6];
    const float* be     = (const float*)d_in[7];
    const float* W1_rel = (const float*)d_in[8];
    const float* W1_edge= (const float*)d_in[9];
    const float* W1_root= (const float*)d_in[10];
    const float* b1     = (const float*)d_in[11];
    const float* W2_rel = (const float*)d_in[12];
    const float* W2_root= (const float*)d_in[13];
    const float* b2     = (const float*)d_in[14];
    const float* Wc     = (const float*)d_in[15];
    const float* bc     = (const float*)d_in[16];
    float* out          = (float*)d_out;

    __half *pmm, *ppp;
    float *pr1, *phpre, *pr2;
    int* pdeg;
    cudaGetSymbolAddress((void**)&pmm,   g_mm);
    cudaGetSymbolAddress((void**)&ppp,   g_pp);
    cudaGetSymbolAddress((void**)&pr1,   g_r1);
    cudaGetSymbolAddress((void**)&phpre, g_hpre);
    cudaGetSymbolAddress((void**)&pr2,   g_r2);
    cudaGetSymbolAddress((void**)&pdeg,  g_deg);

    const int histBlocks     = (NE + 255) / 256;
    const int edgeBlocks     = (NE + 255) / 256;
    const int nodeWarpBlocks = (NN * 32 + 255) / 256;

    cudaMemsetAsync(pdeg, 0, NN * sizeof(int));

    // conv1 node-side HMMA GEMMs (embed fused) + degree hist in tail blocks
    k_conv1_front<<<GEMM_BLKS + histBlocks, 256>>>(
        x, W1_rel, W1_rel + 4096, W1_root, b1, Wn, bn, pmm, pr1, ei);

    // CSR offsets + fill
    k_scan<<<1, 1024>>>();
    k_fill<<<edgeBlocks, 256>>>(ei, ea, et);

    // conv1 gather (sum) + edge-feature fold
    k_gather1<<<nodeWarpBlocks, 256>>>(We, be, W1_edge);

    // conv2 node-side HMMA GEMM: h = relu(hpre) fused
    k_gemm3<<<GEMM_BLKS, 256>>>(phpre, W2_rel, W2_rel + 4096, W2_root, b2,
                                ppp, pr2);

    // conv2 gather (max) + readout fused
    k_gather2<<<nodeWarpBlocks, 256>>>(Wc, bc, out);
}